// round 11
// baseline (speedup 1.0000x reference)
#include <cuda_runtime.h>
#include <cuda_fp16.h>
#include <cstdint>

#define NROWS 8192
#define DDIM  128
#define BMT   128                          // macro-tile rows
#define BNT   256                          // macro-tile cols
#define NTM   (NROWS / BMT)                // 64
#define NTN   (NROWS / BNT)                // 32
#define TOTT  (NTM * NTN)                  // 2048
#define GRIDSZ 148                         // 1 CTA per SM
#define INV_N2 1.4901161193847656e-08f     // 2^-26

#define TILEB_A    32768                   // 128 rows x 256B
#define TILEB_B    65536                   // 256 rows x 256B
#define SMEM_A_OFF 0
#define SMEM_B0_OFF TILEB_A                // 32K
#define SMEM_B1_OFF (TILEB_A + TILEB_B)    // 96K
#define SMEM_RED_OFF (TILEB_A + 2 * TILEB_B)   // 160K
#define SMEM_MBAR_OFF (SMEM_RED_OFF + 64)
#define SMEM_BYTES (SMEM_MBAR_OFF + 64 + 2048)

// fp16 normalized copies, PRE-SWIZZLED: 16B chunk v of row r at slot v^(r&7).
__device__ __half g_xh[NROWS * DDIM];
__device__ __half g_yh[NROWS * DDIM];

__device__ __forceinline__ uint32_t smem_u32(const void* p) {
    uint32_t a;
    asm("{ .reg .u64 t; cvta.to.shared.u64 t, %1; cvt.u32.u64 %0, t; }" : "=r"(a) : "l"(p));
    return a;
}
__device__ __forceinline__ void bulk_g2s(uint32_t dst, const void* src,
                                         uint32_t bytes, uint32_t mbar) {
    asm volatile("cp.async.bulk.shared::cta.global.mbarrier::complete_tx::bytes "
                 "[%0], [%1], %2, [%3];"
                 :: "r"(dst), "l"(src), "r"(bytes), "r"(mbar) : "memory");
}
#define MBARRIER_INIT(mbar, count) \
    asm volatile("mbarrier.init.shared.b64 [%0], %1;" :: "r"((uint32_t)(mbar)), "r"((uint32_t)(count)) : "memory")
#define MBARRIER_EXPECT_TX(mbar, bytes) \
    asm volatile("mbarrier.arrive.expect_tx.shared.b64 _, [%0], %1;" :: "r"((uint32_t)(mbar)), "r"((uint32_t)(bytes)) : "memory")
#define MBARRIER_ARRIVE(mbar) \
    asm volatile("mbarrier.arrive.shared.b64 _, [%0];" :: "r"((uint32_t)(mbar)) : "memory")

#define MBARRIER_WAIT_PARITY(mbar_smem_addr, phase_parity) do { \
    uint32_t _mbar = (uint32_t)(mbar_smem_addr); \
    uint32_t _parity = (uint32_t)(phase_parity); \
    uint32_t _done; \
    asm volatile("{\n\t.reg .pred p;\n\t" \
        "mbarrier.try_wait.parity.acquire.cta.shared::cta.b64 p, [%1], %2;\n\t" \
        "selp.b32 %0, 1, 0, p;\n\t}" : "=r"(_done) : "r"(_mbar), "r"(_parity) : "memory"); \
    if (!_done) { \
        asm volatile("{\n\t.reg .pred P1;\n\t" \
            "WAIT_LOOP_%=:\n\t" \
            "mbarrier.try_wait.parity.acquire.cta.shared::cta.b64 P1, [%0], %1, 0x989680;\n\t" \
            "@P1 bra.uni WAIT_DONE_%=;\n\t" \
            "bra.uni WAIT_LOOP_%=;\n\t" \
            "WAIT_DONE_%=:\n\t}" :: "r"(_mbar), "r"(_parity) : "memory"); \
    } \
} while(0)

// Relaxed: producer-only; post-wait smem access is async-proxy (bulk copy).
#define MBARRIER_WAIT_PARITY_RELAXED(mbar_smem_addr, phase_parity) do { \
    uint32_t _mbar = (uint32_t)(mbar_smem_addr); \
    uint32_t _parity = (uint32_t)(phase_parity); \
    uint32_t _done; \
    asm volatile("{\n\t.reg .pred p;\n\t" \
        "mbarrier.try_wait.parity.relaxed.cta.shared::cta.b64 p, [%1], %2, 0x989680;\n\t" \
        "selp.b32 %0, 1, 0, p;\n\t}" : "=r"(_done) : "r"(_mbar), "r"(_parity) : "memory"); \
    if (!_done) { \
        asm volatile("{\n\t.reg .pred P1;\n\t" \
            "WAIT_LOOP_%=:\n\t" \
            "mbarrier.try_wait.parity.relaxed.cta.shared::cta.b64 P1, [%0], %1, 0x989680;\n\t" \
            "@P1 bra.uni WAIT_DONE_%=;\n\t" \
            "bra.uni WAIT_LOOP_%=;\n\t" \
            "WAIT_DONE_%=:\n\t}" :: "r"(_mbar), "r"(_parity) : "memory"); \
    } \
} while(0)

__device__ __forceinline__ void ldmatrix_x4(uint32_t& r0, uint32_t& r1,
                                            uint32_t& r2, uint32_t& r3, uint32_t addr) {
    asm volatile("ldmatrix.sync.aligned.m8n8.x4.shared.b16 {%0,%1,%2,%3}, [%4];"
                 : "=r"(r0), "=r"(r1), "=r"(r2), "=r"(r3) : "r"(addr));
}
// fp16-accumulate MMA: 2x issue rate vs fp32-acc form.
__device__ __forceinline__ void mma16816_f16(uint32_t& d0, uint32_t& d1,
                                             uint32_t a0, uint32_t a1, uint32_t a2, uint32_t a3,
                                             uint32_t b0, uint32_t b1) {
    asm volatile("mma.sync.aligned.m16n8k16.row.col.f16.f16.f16.f16 "
                 "{%0,%1}, {%2,%3,%4,%5}, {%6,%7}, {%0,%1};"
                 : "+r"(d0), "+r"(d1)
                 : "r"(a0), "r"(a1), "r"(a2), "r"(a3), "r"(b0), "r"(b1));
}

// ---------------------------------------------------------------------------
// Kernel A: warp-per-row normalize; fp16 output, swizzled gmem layout.
// ---------------------------------------------------------------------------
__global__ void __launch_bounds__(256)
normalize_kernel(const float* __restrict__ x, const float* __restrict__ y) {
    const int row  = blockIdx.x * 8 + (threadIdx.x >> 5);
    const int lane = threadIdx.x & 31;
    const float* src;
    __half* dst;
    if (row < NROWS) { src = x + (size_t)row * DDIM;           dst = g_xh + (size_t)row * DDIM; }
    else             { src = y + (size_t)(row - NROWS) * DDIM; dst = g_yh + (size_t)(row - NROWS) * DDIM; }

    float4 v = ((const float4*)src)[lane];
    float ss = v.x * v.x + v.y * v.y + v.z * v.z + v.w * v.w;
    #pragma unroll
    for (int o = 16; o > 0; o >>= 1) ss += __shfl_xor_sync(0xffffffffu, ss, o);
    float r = rsqrtf(fmaxf(ss, 1e-24f));

    __half2 p0 = __floats2half2_rn(v.x * r, v.y * r);
    __half2 p1 = __floats2half2_rn(v.z * r, v.w * r);
    uint2 pk;
    pk.x = *(uint32_t*)&p0;
    pk.y = *(uint32_t*)&p1;

    const int vchunk = lane >> 1;
    const int half_i = lane & 1;
    const int schunk = vchunk ^ (row & 7);
    ((uint2*)dst)[schunk * 2 + half_i] = pk;
}

// ---------------------------------------------------------------------------
// Kernel B: persistent fp16 mma.sync GEMM (fp16 accumulate) + fused loss.
// CTA macro-tile 128x256; 8 warps 2(m) x 4(n), warp tile 64x64.
// Per-warp producer/consumer mbarrier pipeline; B double-buffered.
// ---------------------------------------------------------------------------
extern __shared__ char dyn_smem[];

__global__ void __launch_bounds__(256, 1)
gemm_loss_kernel(float* __restrict__ out) {
    const int tid  = threadIdx.x;
    const int warp = tid >> 5;
    const int lane = tid & 31;
    const int wm = warp >> 2;          // 0..1  (64-row half)
    const int wn = warp & 3;           // 0..3  (64-col quarter)

    const uint32_t sbase = (smem_u32(dyn_smem) + 2047u) & ~2047u;
    const uint32_t sA   = sbase + SMEM_A_OFF;
    const uint32_t sB0  = sbase + SMEM_B0_OFF;
    const uint32_t sB1  = sbase + SMEM_B1_OFF;
    const uint32_t full0  = sbase + SMEM_MBAR_OFF;
    const uint32_t full1  = full0 + 8;
    const uint32_t empty0 = full0 + 16;
    const uint32_t empty1 = full0 + 24;

    if (tid == 0) {
        MBARRIER_INIT(full0, 1);
        MBARRIER_INIT(full1, 1);
        MBARRIER_INIT(empty0, 8);
        MBARRIER_INIT(empty1, 8);
    }
    __syncthreads();

    // ldmatrix addressing (swizzled): addr = tile + row*256 + (col ^ (t8<<4))
    const int t8 = lane & 7;
    const uint32_t sxor = (uint32_t)t8 << 4;
    const uint32_t aRow = (uint32_t)(wm * 64 + t8 + ((lane >> 3) & 1) * 8);
    const uint32_t aRB  = aRow * 256;
    const uint32_t aCol = (uint32_t)(lane >> 4) * 16;
    const uint32_t bRow = (uint32_t)(wn * 64 + ((lane >> 4) * 8) + t8);
    const uint32_t bRB  = bRow * 256;
    const uint32_t bCol = (uint32_t)((lane >> 3) & 1) * 16;

    // balanced tile split: 2048 tiles over 148 CTAs
    const int per = TOTT / GRIDSZ;                 // 13
    const int rem = TOTT - per * GRIDSZ;           // 124
    int start, cnt;
    if ((int)blockIdx.x < rem) { cnt = per + 1; start = blockIdx.x * cnt; }
    else                       { cnt = per;     start = rem * (per + 1) + ((int)blockIdx.x - rem) * per; }

    // 8 persistent fp32 partial sums (breaks serial FADD chains)
    float ps[8];
    #pragma unroll
    for (int i = 0; i < 8; i++) ps[i] = 0.0f;

    int cur_bm = -1;

    for (int k = 0; k < cnt; k++) {
        const int t  = start + k;
        const int bm = t >> 5;                     // 32 n-tiles per bm row
        const int bn = t & 31;
        const int buf = t & 1;
        const uint32_t sBcur = buf ? sB1 : sB0;
        const uint32_t fcur  = buf ? full1 : full0;

        if (bm != cur_bm) {
            __syncthreads();                       // rare: old A must be dead
            if (tid == 0) {
                const int pf = k >> 1;
                if (pf > 0) {
                    const uint32_t ecur = buf ? empty1 : empty0;
                    MBARRIER_WAIT_PARITY_RELAXED(ecur, (pf - 1) & 1);
                }
                MBARRIER_EXPECT_TX(fcur, TILEB_A + TILEB_B);
                bulk_g2s(sA,    g_xh + (size_t)bm * BMT * DDIM, TILEB_A, fcur);
                bulk_g2s(sBcur, g_yh + (size_t)bn * BNT * DDIM, TILEB_B, fcur);
            }
            cur_bm = bm;
        }

        // producer: fill B(t+1) if next tile shares this A row
        if (tid == 0 && k + 1 < cnt && ((t + 1) >> 5) == bm) {
            const int nbuf = (t + 1) & 1;
            const uint32_t fn = nbuf ? full1 : full0;
            const uint32_t en = nbuf ? empty1 : empty0;
            const int pf = (k + 1) >> 1;
            if (pf > 0) MBARRIER_WAIT_PARITY_RELAXED(en, (pf - 1) & 1);
            MBARRIER_EXPECT_TX(fn, TILEB_B);
            bulk_g2s(nbuf ? sB1 : sB0,
                     g_yh + (size_t)((t + 1) & 31) * BNT * DDIM, TILEB_B, fn);
        }

        // consumer: per-warp wait for this tile's data
        MBARRIER_WAIT_PARITY(fcur, (k >> 1) & 1);

        // ---- MMA: 8 k-steps of 16; fp16 accumulators (2 regs per fragment) ----
        uint32_t acc[4][8][2];
        #pragma unroll
        for (int i = 0; i < 4; i++)
            #pragma unroll
            for (int j = 0; j < 8; j++) { acc[i][j][0] = 0u; acc[i][j][1] = 0u; }

        #pragma unroll
        for (int ks = 0; ks < 8; ks++) {
            const uint32_t ko = (uint32_t)ks * 32;
            uint32_t a[4][4];
            uint32_t b[4][4];
            #pragma unroll
            for (int mt = 0; mt < 4; mt++)
                ldmatrix_x4(a[mt][0], a[mt][1], a[mt][2], a[mt][3],
                            sA + aRB + (uint32_t)(mt * 4096) + ((aCol + ko) ^ sxor));
            #pragma unroll
            for (int bi = 0; bi < 4; bi++)
                ldmatrix_x4(b[bi][0], b[bi][1], b[bi][2], b[bi][3],
                            sBcur + bRB + (uint32_t)(bi * 4096) + ((bCol + ko) ^ sxor));

            // after the last k-step's LDSMs, B is fully in registers
            if (ks == 7 && lane == 0) MBARRIER_ARRIVE(buf ? empty1 : empty0);

            #pragma unroll
            for (int mt = 0; mt < 4; mt++) {
                #pragma unroll
                for (int nt = 0; nt < 8; nt++) {
                    const int bi = nt >> 1;
                    const int po = (nt & 1) * 2;
                    mma16816_f16(acc[mt][nt][0], acc[mt][nt][1],
                                 a[mt][0], a[mt][1], a[mt][2], a[mt][3],
                                 b[bi][po], b[bi][po + 1]);
                }
            }
        }

        // ---- fused loss map (convert half2 -> float2) into partials ----
        if ((bm >> 1) != bn) {
            #pragma unroll
            for (int mt = 0; mt < 4; mt++) {
                #pragma unroll
                for (int nt = 0; nt < 8; nt++) {
                    float2 lo = __half22float2(*(__half2*)&acc[mt][nt][0]);
                    float2 hi = __half22float2(*(__half2*)&acc[mt][nt][1]);
                    const int pb = (nt & 1) << 2;
                    ps[pb | 0] += fmaxf(lo.x, 0.0f);
                    ps[pb | 1] += fmaxf(lo.y, 0.0f);
                    ps[pb | 2] += fmaxf(hi.x, 0.0f);
                    ps[pb | 3] += fmaxf(hi.y, 0.0f);
                }
            }
        } else {
            const int gm0 = bm * BMT + wm * 64 + (lane >> 2);
            const int gn0 = bn * BNT + wn * 64 + (lane & 3) * 2;
            #pragma unroll
            for (int mt = 0; mt < 4; mt++) {
                const int gmA = gm0 + mt * 16;
                const int gmB = gmA + 8;
                #pragma unroll
                for (int nt = 0; nt < 8; nt++) {
                    const int gn = gn0 + nt * 8;
                    float2 lo = __half22float2(*(__half2*)&acc[mt][nt][0]);
                    float2 hi = __half22float2(*(__half2*)&acc[mt][nt][1]);
                    const int pb = (nt & 1) << 2;
                    ps[pb | 0] += (gmA == gn    ) ? (1.0f - lo.x) : fmaxf(lo.x, 0.0f);
                    ps[pb | 1] += (gmA == gn + 1) ? (1.0f - lo.y) : fmaxf(lo.y, 0.0f);
                    ps[pb | 2] += (gmB == gn    ) ? (1.0f - hi.x) : fmaxf(hi.x, 0.0f);
                    ps[pb | 3] += (gmB == gn + 1) ? (1.0f - hi.y) : fmaxf(hi.y, 0.0f);
                }
            }
        }
    }

    // ---- combine partials, block reduction + single atomic ----
    float lsum = ((ps[0] + ps[1]) + (ps[2] + ps[3]))
               + ((ps[4] + ps[5]) + (ps[6] + ps[7]));
    #pragma unroll
    for (int o = 16; o > 0; o >>= 1) lsum += __shfl_xor_sync(0xffffffffu, lsum, o);
    float* red = (float*)(uintptr_t)(dyn_smem + (sbase - smem_u32(dyn_smem)) + SMEM_RED_OFF);
    __syncthreads();
    if (lane == 0) red[warp] = lsum;
    __syncthreads();
    if (tid == 0) {
        float tot = 0.0f;
        #pragma unroll
        for (int w = 0; w < 8; w++) tot += red[w];
        atomicAdd(out, tot * INV_N2);
    }
}

// ---------------------------------------------------------------------------
extern "C" void kernel_launch(void* const* d_in, const int* in_sizes, int n_in,
                              void* d_out, int out_size) {
    const float* x = (const float*)d_in[0];
    const float* y = (const float*)d_in[1];
    float* out = (float*)d_out;

    cudaFuncSetAttribute(gemm_loss_kernel,
                         cudaFuncAttributeMaxDynamicSharedMemorySize, SMEM_BYTES);

    cudaMemsetAsync(out, 0, sizeof(float));
    normalize_kernel<<<2 * NROWS / 8, 256>>>(x, y);
    gemm_loss_kernel<<<GRIDSZ, 256, SMEM_BYTES>>>(out);
}

// round 12
// speedup vs baseline: 1.0137x; 1.0137x over previous
#include <cuda_runtime.h>
#include <cuda_fp16.h>
#include <cstdint>

#define NROWS 8192
#define DDIM  128
#define BMT   128                          // macro-tile rows
#define BNT   256                          // macro-tile cols
#define NTM   (NROWS / BMT)                // 64
#define NTN   (NROWS / BNT)                // 32
#define TOTT  (NTM * NTN)                  // 2048
#define GRIDSZ 148                         // 1 CTA per SM
#define INV_N2 1.4901161193847656e-08f     // 2^-26

#define TILEB_A    32768                   // 128 rows x 256B
#define TILEB_B    65536                   // 256 rows x 256B
#define SMEM_A_OFF 0
#define SMEM_B0_OFF TILEB_A                // 32K
#define SMEM_B1_OFF (TILEB_A + TILEB_B)    // 96K
#define SMEM_RED_OFF (TILEB_A + 2 * TILEB_B)   // 160K
#define SMEM_MBAR_OFF (SMEM_RED_OFF + 64)
#define SMEM_BYTES (SMEM_MBAR_OFF + 64 + 2048)

// fp16 normalized copies, PRE-SWIZZLED: 16B chunk v of row r at slot v^(r&7).
__device__ __half g_xh[NROWS * DDIM];
__device__ __half g_yh[NROWS * DDIM];

__device__ __forceinline__ uint32_t smem_u32(const void* p) {
    uint32_t a;
    asm("{ .reg .u64 t; cvta.to.shared.u64 t, %1; cvt.u32.u64 %0, t; }" : "=r"(a) : "l"(p));
    return a;
}
__device__ __forceinline__ void bulk_g2s(uint32_t dst, const void* src,
                                         uint32_t bytes, uint32_t mbar) {
    asm volatile("cp.async.bulk.shared::cta.global.mbarrier::complete_tx::bytes "
                 "[%0], [%1], %2, [%3];"
                 :: "r"(dst), "l"(src), "r"(bytes), "r"(mbar) : "memory");
}
#define MBARRIER_INIT(mbar, count) \
    asm volatile("mbarrier.init.shared.b64 [%0], %1;" :: "r"((uint32_t)(mbar)), "r"((uint32_t)(count)) : "memory")
#define MBARRIER_EXPECT_TX(mbar, bytes) \
    asm volatile("mbarrier.arrive.expect_tx.shared.b64 _, [%0], %1;" :: "r"((uint32_t)(mbar)), "r"((uint32_t)(bytes)) : "memory")
#define MBARRIER_ARRIVE(mbar) \
    asm volatile("mbarrier.arrive.shared.b64 _, [%0];" :: "r"((uint32_t)(mbar)) : "memory")

#define MBARRIER_WAIT_PARITY(mbar_smem_addr, phase_parity) do { \
    uint32_t _mbar = (uint32_t)(mbar_smem_addr); \
    uint32_t _parity = (uint32_t)(phase_parity); \
    uint32_t _done; \
    asm volatile("{\n\t.reg .pred p;\n\t" \
        "mbarrier.try_wait.parity.acquire.cta.shared::cta.b64 p, [%1], %2;\n\t" \
        "selp.b32 %0, 1, 0, p;\n\t}" : "=r"(_done) : "r"(_mbar), "r"(_parity) : "memory"); \
    if (!_done) { \
        asm volatile("{\n\t.reg .pred P1;\n\t" \
            "WAIT_LOOP_%=:\n\t" \
            "mbarrier.try_wait.parity.acquire.cta.shared::cta.b64 P1, [%0], %1, 0x989680;\n\t" \
            "@P1 bra.uni WAIT_DONE_%=;\n\t" \
            "bra.uni WAIT_LOOP_%=;\n\t" \
            "WAIT_DONE_%=:\n\t}" :: "r"(_mbar), "r"(_parity) : "memory"); \
    } \
} while(0)

// Relaxed: producer-only; post-wait smem access is async-proxy (bulk copy).
#define MBARRIER_WAIT_PARITY_RELAXED(mbar_smem_addr, phase_parity) do { \
    uint32_t _mbar = (uint32_t)(mbar_smem_addr); \
    uint32_t _parity = (uint32_t)(phase_parity); \
    uint32_t _done; \
    asm volatile("{\n\t.reg .pred p;\n\t" \
        "mbarrier.try_wait.parity.relaxed.cta.shared::cta.b64 p, [%1], %2, 0x989680;\n\t" \
        "selp.b32 %0, 1, 0, p;\n\t}" : "=r"(_done) : "r"(_mbar), "r"(_parity) : "memory"); \
    if (!_done) { \
        asm volatile("{\n\t.reg .pred P1;\n\t" \
            "WAIT_LOOP_%=:\n\t" \
            "mbarrier.try_wait.parity.relaxed.cta.shared::cta.b64 P1, [%0], %1, 0x989680;\n\t" \
            "@P1 bra.uni WAIT_DONE_%=;\n\t" \
            "bra.uni WAIT_LOOP_%=;\n\t" \
            "WAIT_DONE_%=:\n\t}" :: "r"(_mbar), "r"(_parity) : "memory"); \
    } \
} while(0)

__device__ __forceinline__ void ldmatrix_x4(uint32_t& r0, uint32_t& r1,
                                            uint32_t& r2, uint32_t& r3, uint32_t addr) {
    asm volatile("ldmatrix.sync.aligned.m8n8.x4.shared.b16 {%0,%1,%2,%3}, [%4];"
                 : "=r"(r0), "=r"(r1), "=r"(r2), "=r"(r3) : "r"(addr));
}
// fp16-accumulate MMA: 2x issue rate vs fp32-acc form.
__device__ __forceinline__ void mma16816_f16(uint32_t& d0, uint32_t& d1,
                                             uint32_t a0, uint32_t a1, uint32_t a2, uint32_t a3,
                                             uint32_t b0, uint32_t b1) {
    asm volatile("mma.sync.aligned.m16n8k16.row.col.f16.f16.f16.f16 "
                 "{%0,%1}, {%2,%3,%4,%5}, {%6,%7}, {%0,%1};"
                 : "+r"(d0), "+r"(d1)
                 : "r"(a0), "r"(a1), "r"(a2), "r"(a3), "r"(b0), "r"(b1));
}

// ---------------------------------------------------------------------------
// Kernel A: warp-per-row normalize; fp16 output, swizzled gmem layout.
// ---------------------------------------------------------------------------
__global__ void __launch_bounds__(256)
normalize_kernel(const float* __restrict__ x, const float* __restrict__ y) {
    const int row  = blockIdx.x * 8 + (threadIdx.x >> 5);
    const int lane = threadIdx.x & 31;
    const float* src;
    __half* dst;
    if (row < NROWS) { src = x + (size_t)row * DDIM;           dst = g_xh + (size_t)row * DDIM; }
    else             { src = y + (size_t)(row - NROWS) * DDIM; dst = g_yh + (size_t)(row - NROWS) * DDIM; }

    float4 v = ((const float4*)src)[lane];
    float ss = v.x * v.x + v.y * v.y + v.z * v.z + v.w * v.w;
    #pragma unroll
    for (int o = 16; o > 0; o >>= 1) ss += __shfl_xor_sync(0xffffffffu, ss, o);
    float r = rsqrtf(fmaxf(ss, 1e-24f));

    __half2 p0 = __floats2half2_rn(v.x * r, v.y * r);
    __half2 p1 = __floats2half2_rn(v.z * r, v.w * r);
    uint2 pk;
    pk.x = *(uint32_t*)&p0;
    pk.y = *(uint32_t*)&p1;

    const int vchunk = lane >> 1;
    const int half_i = lane & 1;
    const int schunk = vchunk ^ (row & 7);
    ((uint2*)dst)[schunk * 2 + half_i] = pk;
}

// ---------------------------------------------------------------------------
// Kernel B: persistent fp16 mma.sync GEMM (fp16 accumulate) + fused loss.
// CTA macro-tile 128x256; 8 warps 2(m) x 4(n), warp tile 64x64.
// Per-warp producer/consumer mbarrier pipeline; B double-buffered.
// ---------------------------------------------------------------------------
extern __shared__ char dyn_smem[];

__global__ void __launch_bounds__(256, 1)
gemm_loss_kernel(float* __restrict__ out) {
    const int tid  = threadIdx.x;
    const int warp = tid >> 5;
    const int lane = tid & 31;
    const int wm = warp >> 2;          // 0..1  (64-row half)
    const int wn = warp & 3;           // 0..3  (64-col quarter)

    const uint32_t sbase = (smem_u32(dyn_smem) + 2047u) & ~2047u;
    const uint32_t sA   = sbase + SMEM_A_OFF;
    const uint32_t sB0  = sbase + SMEM_B0_OFF;
    const uint32_t sB1  = sbase + SMEM_B1_OFF;
    const uint32_t full0  = sbase + SMEM_MBAR_OFF;
    const uint32_t full1  = full0 + 8;
    const uint32_t empty0 = full0 + 16;
    const uint32_t empty1 = full0 + 24;

    if (tid == 0) {
        MBARRIER_INIT(full0, 1);
        MBARRIER_INIT(full1, 1);
        MBARRIER_INIT(empty0, 8);
        MBARRIER_INIT(empty1, 8);
    }
    __syncthreads();

    // ldmatrix addressing (swizzled): addr = tile + row*256 + (col ^ (t8<<4))
    const int t8 = lane & 7;
    const uint32_t sxor = (uint32_t)t8 << 4;
    const uint32_t aRow = (uint32_t)(wm * 64 + t8 + ((lane >> 3) & 1) * 8);
    const uint32_t aRB  = aRow * 256;
    const uint32_t aCol = (uint32_t)(lane >> 4) * 16;
    const uint32_t bRow = (uint32_t)(wn * 64 + ((lane >> 4) * 8) + t8);
    const uint32_t bRB  = bRow * 256;
    const uint32_t bCol = (uint32_t)((lane >> 3) & 1) * 16;

    // balanced tile split: 2048 tiles over 148 CTAs
    const int per = TOTT / GRIDSZ;                 // 13
    const int rem = TOTT - per * GRIDSZ;           // 124
    int start, cnt;
    if ((int)blockIdx.x < rem) { cnt = per + 1; start = blockIdx.x * cnt; }
    else                       { cnt = per;     start = rem * (per + 1) + ((int)blockIdx.x - rem) * per; }

    // 8 persistent fp32 partial sums (breaks serial FADD chains)
    float ps[8];
    #pragma unroll
    for (int i = 0; i < 8; i++) ps[i] = 0.0f;

    int cur_bm = -1;

    for (int k = 0; k < cnt; k++) {
        const int t  = start + k;
        const int bm = t >> 5;                     // 32 n-tiles per bm row
        const int bn = t & 31;
        const int buf = t & 1;
        const uint32_t sBcur = buf ? sB1 : sB0;
        const uint32_t fcur  = buf ? full1 : full0;

        if (bm != cur_bm) {
            __syncthreads();                       // rare: old A must be dead
            if (tid == 0) {
                const int pf = k >> 1;
                if (pf > 0) {
                    const uint32_t ecur = buf ? empty1 : empty0;
                    MBARRIER_WAIT_PARITY_RELAXED(ecur, (pf - 1) & 1);
                }
                MBARRIER_EXPECT_TX(fcur, TILEB_A + TILEB_B);
                bulk_g2s(sA,    g_xh + (size_t)bm * BMT * DDIM, TILEB_A, fcur);
                bulk_g2s(sBcur, g_yh + (size_t)bn * BNT * DDIM, TILEB_B, fcur);
            }
            cur_bm = bm;
        }

        // producer: fill B(t+1) if next tile shares this A row
        if (tid == 0 && k + 1 < cnt && ((t + 1) >> 5) == bm) {
            const int nbuf = (t + 1) & 1;
            const uint32_t fn = nbuf ? full1 : full0;
            const uint32_t en = nbuf ? empty1 : empty0;
            const int pf = (k + 1) >> 1;
            if (pf > 0) MBARRIER_WAIT_PARITY_RELAXED(en, (pf - 1) & 1);
            MBARRIER_EXPECT_TX(fn, TILEB_B);
            bulk_g2s(nbuf ? sB1 : sB0,
                     g_yh + (size_t)((t + 1) & 31) * BNT * DDIM, TILEB_B, fn);
        }

        // consumer: per-warp wait for this tile's data
        MBARRIER_WAIT_PARITY(fcur, (k >> 1) & 1);

        // ---- MMA: 8 k-steps of 16; fp16 accumulators (2 regs per fragment) ----
        uint32_t acc[4][8][2];
        #pragma unroll
        for (int i = 0; i < 4; i++)
            #pragma unroll
            for (int j = 0; j < 8; j++) { acc[i][j][0] = 0u; acc[i][j][1] = 0u; }

        #pragma unroll
        for (int ks = 0; ks < 8; ks++) {
            const uint32_t ko = (uint32_t)ks * 32;
            uint32_t a[4][4];
            uint32_t b[4][4];
            #pragma unroll
            for (int mt = 0; mt < 4; mt++)
                ldmatrix_x4(a[mt][0], a[mt][1], a[mt][2], a[mt][3],
                            sA + aRB + (uint32_t)(mt * 4096) + ((aCol + ko) ^ sxor));
            #pragma unroll
            for (int bi = 0; bi < 4; bi++)
                ldmatrix_x4(b[bi][0], b[bi][1], b[bi][2], b[bi][3],
                            sBcur + bRB + (uint32_t)(bi * 4096) + ((bCol + ko) ^ sxor));

            // after the last k-step's LDSMs, B is fully in registers
            if (ks == 7 && lane == 0) MBARRIER_ARRIVE(buf ? empty1 : empty0);

            #pragma unroll
            for (int mt = 0; mt < 4; mt++) {
                #pragma unroll
                for (int nt = 0; nt < 8; nt++) {
                    const int bi = nt >> 1;
                    const int po = (nt & 1) * 2;
                    mma16816_f16(acc[mt][nt][0], acc[mt][nt][1],
                                 a[mt][0], a[mt][1], a[mt][2], a[mt][3],
                                 b[bi][po], b[bi][po + 1]);
                }
            }
        }

        // ---- fused loss map (convert half2 -> float2) into partials ----
        if ((bm >> 1) != bn) {
            #pragma unroll
            for (int mt = 0; mt < 4; mt++) {
                #pragma unroll
                for (int nt = 0; nt < 8; nt++) {
                    float2 lo = __half22float2(*(__half2*)&acc[mt][nt][0]);
                    float2 hi = __half22float2(*(__half2*)&acc[mt][nt][1]);
                    const int pb = (nt & 1) << 2;
                    ps[pb | 0] += fmaxf(lo.x, 0.0f);
                    ps[pb | 1] += fmaxf(lo.y, 0.0f);
                    ps[pb | 2] += fmaxf(hi.x, 0.0f);
                    ps[pb | 3] += fmaxf(hi.y, 0.0f);
                }
            }
        } else {
            const int gm0 = bm * BMT + wm * 64 + (lane >> 2);
            const int gn0 = bn * BNT + wn * 64 + (lane & 3) * 2;
            #pragma unroll
            for (int mt = 0; mt < 4; mt++) {
                const int gmA = gm0 + mt * 16;
                const int gmB = gmA + 8;
                #pragma unroll
                for (int nt = 0; nt < 8; nt++) {
                    const int gn = gn0 + nt * 8;
                    float2 lo = __half22float2(*(__half2*)&acc[mt][nt][0]);
                    float2 hi = __half22float2(*(__half2*)&acc[mt][nt][1]);
                    const int pb = (nt & 1) << 2;
                    ps[pb | 0] += (gmA == gn    ) ? (1.0f - lo.x) : fmaxf(lo.x, 0.0f);
                    ps[pb | 1] += (gmA == gn + 1) ? (1.0f - lo.y) : fmaxf(lo.y, 0.0f);
                    ps[pb | 2] += (gmB == gn    ) ? (1.0f - hi.x) : fmaxf(hi.x, 0.0f);
                    ps[pb | 3] += (gmB == gn + 1) ? (1.0f - hi.y) : fmaxf(hi.y, 0.0f);
                }
            }
        }
    }

    // ---- combine partials, block reduction + single atomic ----
    float lsum = ((ps[0] + ps[1]) + (ps[2] + ps[3]))
               + ((ps[4] + ps[5]) + (ps[6] + ps[7]));
    #pragma unroll
    for (int o = 16; o > 0; o >>= 1) lsum += __shfl_xor_sync(0xffffffffu, lsum, o);
    float* red = (float*)(uintptr_t)(dyn_smem + (sbase - smem_u32(dyn_smem)) + SMEM_RED_OFF);
    __syncthreads();
    if (lane == 0) red[warp] = lsum;
    __syncthreads();
    if (tid == 0) {
        float tot = 0.0f;
        #pragma unroll
        for (int w = 0; w < 8; w++) tot += red[w];
        atomicAdd(out, tot * INV_N2);
    }
}

// ---------------------------------------------------------------------------
extern "C" void kernel_launch(void* const* d_in, const int* in_sizes, int n_in,
                              void* d_out, int out_size) {
    const float* x = (const float*)d_in[0];
    const float* y = (const float*)d_in[1];
    float* out = (float*)d_out;

    cudaFuncSetAttribute(gemm_loss_kernel,
                         cudaFuncAttributeMaxDynamicSharedMemorySize, SMEM_BYTES);

    cudaMemsetAsync(out, 0, sizeof(float));
    normalize_kernel<<<2 * NROWS / 8, 256>>>(x, y);
    gemm_loss_kernel<<<GRIDSZ, 256, SMEM_BYTES>>>(out);
}